// round 15
// baseline (speedup 1.0000x reference)
#include <cuda_runtime.h>

#define N3 262144
#define N2 65536
#define N1 16384

typedef unsigned long long ull;

// ---------------- scratch (device globals; no allocations allowed) ----------
__device__ float g_x8   [N3 * 16];
__device__ float g_x7p  [N2 * 16];
__device__ float g_x7   [N2 * 32];
__device__ float g_x6p  [N1 * 32];
__device__ float g_x6   [N1 * 64];
__device__ float g_x7dec[N2 * 32];
__device__ float g_x8dec[N3 * 16];
__device__ int   g_pidx3[N3];
__device__ int   g_pidx2[N2];

// ---------------- packed f32x2 helpers ---------------------------------------
__device__ __forceinline__ ull pack2(float lo, float hi) {
    ull r;
    asm("mov.b64 %0, {%1, %2};" : "=l"(r) : "f"(lo), "f"(hi));
    return r;
}
__device__ __forceinline__ ull bcast2(float v) {
    ull r;
    asm("mov.b64 %0, {%1, %1};" : "=l"(r) : "f"(v));
    return r;
}
__device__ __forceinline__ void ffma2(ull& d, ull a, ull b) {
    asm("fma.rn.f32x2 %0, %1, %2, %0;" : "+l"(d) : "l"(a), "l"(b));
}
__device__ __forceinline__ float2 unpack2(ull v) {
    float2 r;
    asm("mov.b64 {%0, %1}, %2;" : "=f"(r.x), "=f"(r.y) : "l"(v));
    return r;
}

// ---------------- fused prep: pidx3, pidx2, zero x7p, zero x6p ---------------
__device__ __forceinline__ int lower_bound_shift(const int* __restrict__ keys,
                                                 int Np, int v) {
    int lo = 0, hi = Np;
    while (lo < hi) {
        int mid = (lo + hi) >> 1;
        if (keys[mid] < v) lo = mid + 1; else hi = mid;
    }
    return lo;
}

__global__ void prep_kernel(const int* __restrict__ keys3,
                            const int* __restrict__ keys2,
                            const int* __restrict__ keys1,
                            int* __restrict__ pidx3, int* __restrict__ pidx2,
                            float* __restrict__ x7p, float* __restrict__ x6p) {
    const int T0 = N3;
    const int T1 = T0 + N2;
    const int T2 = T1 + N2 * 16;
    const int T3 = T2 + N1 * 32;
    int i = blockIdx.x * blockDim.x + threadIdx.x;
    int stride = gridDim.x * blockDim.x;
    for (; i < T3; i += stride) {
        if (i < T0) {
            pidx3[i] = lower_bound_shift(keys2, N2, keys3[i] >> 2);
        } else if (i < T1) {
            int k = i - T0;
            pidx2[k] = lower_bound_shift(keys1, N1, keys2[k] >> 2);
        } else if (i < T2) {
            x7p[i - T1] = 0.0f;
        } else {
            x6p[i - T2] = 0.0f;
        }
    }
}

// segment-max pool. Post-ReLU values >= 0, so int-bit atomicMax == float max
// and 0-init matches the reference's (-inf -> 0) fill.
template <int C>
__global__ void pool_kernel(const float* __restrict__ child,
                            const int* __restrict__ pidx,
                            int Nc, int Np, float* __restrict__ parent) {
    int i = blockIdx.x * blockDim.x + threadIdx.x;
    if (i >= Nc * C) return;
    int node = i / C;
    int c = i - node * C;
    int p = pidx[node];
    if (p < Np) {
        float v = child[i];
        atomicMax(reinterpret_cast<int*>(&parent[(size_t)p * C + c]),
                  __float_as_int(v));
    }
}

// ---------------- fused gather + (9*CIN -> COUT) conv ------------------------
// OS = output-split: OS consecutive lanes share one node; lane `sub` owns
// output channels [sub*COUT/OS, (sub+1)*COUT/OS). The OS lanes load IDENTICAL
// feature addresses -> L1 coalescer merges to one wavefront (no traffic dup),
// and weight LDS touches only OS distinct addresses per instr (crossbar
// dedup). No reduction needed. Packed f32x2 accumulators throughout.
// INDIRECT fuses the unpool gather (row = clamp(pidx[idx])).
template <int CIN, int COB, int OS, int NPN, bool RELU, bool INDIRECT>
__global__ void __launch_bounds__(256)
conv_kernel(const float* __restrict__ feat, const int* __restrict__ neigh,
            const int* __restrict__ pidx, int Nfeat, int ostride,
            const float* __restrict__ w, const float* __restrict__ b,
            float* __restrict__ out) {
    extern __shared__ __align__(16) char smem_raw[];
    const int tid = threadIdx.x;
    const int cin9 = 9 * CIN;

    if constexpr (COB == 1) {
        // head layer: scalar acc, hoisted gather loads per j
        float* ws = reinterpret_cast<float*>(smem_raw);
        for (int s = tid; s < cin9; s += 256) ws[s] = w[s];
        __syncthreads();

        int node[NPN];
        int idx[NPN][9];
#pragma unroll
        for (int t = 0; t < NPN; t++) {
            node[t] = blockIdx.x * (256 * NPN) + t * 256 + tid;
#pragma unroll
            for (int j = 0; j < 9; j++)
                idx[t][j] = neigh[(size_t)node[t] * 9 + j];
        }
        float acc[NPN];
#pragma unroll
        for (int t = 0; t < NPN; t++) acc[t] = b[0];
        for (int j = 0; j < 9; j++) {
            float4 f[NPN][CIN / 4];
#pragma unroll
            for (int t = 0; t < NPN; t++)
#pragma unroll
                for (int k = 0; k < CIN / 4; k++)
                    f[t][k] = (idx[t][j] >= 0)
                        ? *reinterpret_cast<const float4*>(
                              &feat[(size_t)idx[t][j] * CIN + 4 * k])
                        : make_float4(0.f, 0.f, 0.f, 0.f);
#pragma unroll
            for (int k = 0; k < CIN / 4; k++) {
                float4 wv = *reinterpret_cast<const float4*>(
                    &ws[j * CIN + 4 * k]);
#pragma unroll
                for (int t = 0; t < NPN; t++)
                    acc[t] += f[t][k].x * wv.x + f[t][k].y * wv.y +
                              f[t][k].z * wv.z + f[t][k].w * wv.w;
            }
        }
#pragma unroll
        for (int t = 0; t < NPN; t++)
            out[(size_t)node[t] * ostride] = RELU ? fmaxf(acc[t], 0.f) : acc[t];
    } else {
        constexpr int PAIRS = COB / 2;
        ull* ws = reinterpret_cast<ull*>(smem_raw);
        // ws[rc * PAIRS + o2] = pack(w[2o2][rc], w[2o2+1][rc]), rc = j*CIN+c
        for (int s = tid; s < cin9 * PAIRS; s += 256) {
            int rc = s / PAIRS;
            int o2 = s - rc * PAIRS;
            ws[s] = pack2(w[(size_t)(2 * o2) * cin9 + rc],
                          w[(size_t)(2 * o2 + 1) * cin9 + rc]);
        }
        __syncthreads();

        if constexpr (OS == 1) {
            // enc1 path (CIN==1): NPN nodes/thread, all 9 gathers hoisted
            static_assert(CIN == 1, "OS==1 packed path is CIN==1 only");
            int node[NPN];
            int idx[NPN][9];
#pragma unroll
            for (int t = 0; t < NPN; t++) {
                node[t] = blockIdx.x * (256 * NPN) + t * 256 + tid;
#pragma unroll
                for (int j = 0; j < 9; j++)
                    idx[t][j] = neigh[(size_t)node[t] * 9 + j];
            }
            ull acc2[NPN][PAIRS];
#pragma unroll
            for (int o2 = 0; o2 < PAIRS; o2++) {
                ull bv = pack2(b[2 * o2], b[2 * o2 + 1]);
#pragma unroll
                for (int t = 0; t < NPN; t++) acc2[t][o2] = bv;
            }
            float fv[NPN][9];
#pragma unroll
            for (int t = 0; t < NPN; t++)
#pragma unroll
                for (int j = 0; j < 9; j++)
                    fv[t][j] = (idx[t][j] >= 0) ? __ldg(&feat[idx[t][j]]) : 0.f;
#pragma unroll
            for (int j = 0; j < 9; j++) {
                ull ff[NPN];
#pragma unroll
                for (int t = 0; t < NPN; t++) ff[t] = bcast2(fv[t][j]);
                const ull* wrow = ws + j * PAIRS;
#pragma unroll
                for (int og = 0; og < PAIRS; og += 2) {
                    ulonglong2 wl =
                        *reinterpret_cast<const ulonglong2*>(wrow + og);
#pragma unroll
                    for (int t = 0; t < NPN; t++) {
                        ffma2(acc2[t][og], ff[t], wl.x);
                        ffma2(acc2[t][og + 1], ff[t], wl.y);
                    }
                }
            }
#pragma unroll
            for (int t = 0; t < NPN; t++) {
                float* orow = out + (size_t)node[t] * ostride;
#pragma unroll
                for (int o = 0; o < COB; o += 4) {
                    float2 p0 = unpack2(acc2[t][o / 2]);
                    float2 p1 = unpack2(acc2[t][o / 2 + 1]);
                    float4 v;
                    v.x = RELU ? fmaxf(p0.x, 0.f) : p0.x;
                    v.y = RELU ? fmaxf(p0.y, 0.f) : p0.y;
                    v.z = RELU ? fmaxf(p1.x, 0.f) : p1.x;
                    v.w = RELU ? fmaxf(p1.y, 0.f) : p1.y;
                    *reinterpret_cast<float4*>(orow + o) = v;
                }
            }
        } else {
            // OS output-split path
            constexpr int PAIRS_L = PAIRS / OS;      // pairs owned per lane
            constexpr int CIN4 = CIN / 4;
            constexpr int KC = (CIN4 <= 8) ? CIN4 : 8;
            const int gt = blockIdx.x * 256 + tid;
            const int node = gt / OS;
            const int sub = gt & (OS - 1);
            const int oc0 = sub * (COB / OS);        // first output channel

            int idx[9];
#pragma unroll
            for (int j = 0; j < 9; j++) idx[j] = neigh[(size_t)node * 9 + j];
            if (INDIRECT) {
#pragma unroll
                for (int j = 0; j < 9; j++) {
                    if (idx[j] >= 0) {
                        int p = pidx[idx[j]];
                        idx[j] = p < Nfeat ? p : Nfeat - 1;
                    }
                }
            }

            ull acc2[PAIRS_L];
#pragma unroll
            for (int o2 = 0; o2 < PAIRS_L; o2++)
                acc2[o2] = pack2(b[oc0 + 2 * o2], b[oc0 + 2 * o2 + 1]);

            for (int j = 0; j < 9; j++) {
                const int id = idx[j];
#pragma unroll
                for (int k0 = 0; k0 < CIN4; k0 += KC) {
                    float4 f[KC];
                    // hoisted load phase (identical addrs across OS lanes)
#pragma unroll
                    for (int k = 0; k < KC; k++)
                        f[k] = (id >= 0)
                            ? *reinterpret_cast<const float4*>(
                                  &feat[(size_t)id * CIN + 4 * (k0 + k)])
                            : make_float4(0.f, 0.f, 0.f, 0.f);
                    // FMA phase
#pragma unroll
                    for (int k = 0; k < KC; k++) {
#pragma unroll
                        for (int cc = 0; cc < 4; cc++) {
                            float v = cc == 0 ? f[k].x : cc == 1 ? f[k].y
                                    : cc == 2 ? f[k].z : f[k].w;
                            ull ff = bcast2(v);
                            const ull* wrow = ws +
                                (j * CIN + 4 * (k0 + k) + cc) * PAIRS +
                                sub * PAIRS_L;
#pragma unroll
                            for (int og = 0; og < PAIRS_L; og += 2) {
                                ulonglong2 wl =
                                    *reinterpret_cast<const ulonglong2*>(
                                        wrow + og);
                                ffma2(acc2[og], ff, wl.x);
                                ffma2(acc2[og + 1], ff, wl.y);
                            }
                        }
                    }
                }
            }

            float* orow = out + (size_t)node * ostride + oc0;
#pragma unroll
            for (int o = 0; o < COB / OS; o += 4) {
                float2 p0 = unpack2(acc2[o / 2]);
                float2 p1 = unpack2(acc2[o / 2 + 1]);
                float4 v;
                v.x = RELU ? fmaxf(p0.x, 0.f) : p0.x;
                v.y = RELU ? fmaxf(p0.y, 0.f) : p0.y;
                v.z = RELU ? fmaxf(p1.x, 0.f) : p1.x;
                v.w = RELU ? fmaxf(p1.y, 0.f) : p1.y;
                *reinterpret_cast<float4*>(orow + o) = v;
            }
        }
    }
}

// ---------------- launch ------------------------------------------------------
static inline int cdiv(int a, int b) { return (a + b - 1) / b; }

extern "C" void kernel_launch(void* const* d_in, const int* in_sizes, int n_in,
                              void* d_out, int out_size) {
    const float* features = (const float*)d_in[0];
    const int* keys3   = (const int*)d_in[1];
    const int* keys2   = (const int*)d_in[2];
    const int* keys1   = (const int*)d_in[3];
    const int* neighs3 = (const int*)d_in[4];
    const int* neighs2 = (const int*)d_in[5];
    const int* neighs1 = (const int*)d_in[6];
    const float* w_enc1 = (const float*)d_in[7];
    const float* b_enc1 = (const float*)d_in[8];
    const float* w_enc2 = (const float*)d_in[9];
    const float* b_enc2 = (const float*)d_in[10];
    const float* w_enc3 = (const float*)d_in[11];
    const float* b_enc3 = (const float*)d_in[12];
    const float* w_dec1 = (const float*)d_in[13];
    const float* b_dec1 = (const float*)d_in[14];
    const float* w_dec2 = (const float*)d_in[15];
    const float* b_dec2 = (const float*)d_in[16];
    const float* w_head = (const float*)d_in[17];
    const float* b_head = (const float*)d_in[18];
    float* out = (float*)d_out;

    float *x8, *x7p, *x7, *x6p, *x6, *x7dec, *x8dec;
    int *pidx3, *pidx2;
    cudaGetSymbolAddress((void**)&x8, g_x8);
    cudaGetSymbolAddress((void**)&x7p, g_x7p);
    cudaGetSymbolAddress((void**)&x7, g_x7);
    cudaGetSymbolAddress((void**)&x6p, g_x6p);
    cudaGetSymbolAddress((void**)&x6, g_x6);
    cudaGetSymbolAddress((void**)&x7dec, g_x7dec);
    cudaGetSymbolAddress((void**)&x8dec, g_x8dec);
    cudaGetSymbolAddress((void**)&pidx3, g_pidx3);
    cudaGetSymbolAddress((void**)&pidx2, g_pidx2);

    // 72KB dynamic smem instantiations
    cudaFuncSetAttribute((const void*)conv_kernel<32, 64, 4, 1, true, false>,
                         cudaFuncAttributeMaxDynamicSharedMemorySize, 73728);
    cudaFuncSetAttribute((const void*)conv_kernel<64, 32, 2, 1, true, true>,
                         cudaFuncAttributeMaxDynamicSharedMemorySize, 73728);

    // 0: fused prep (pidx3, pidx2, zero pool accumulators)
    prep_kernel<<<2048, 256>>>(keys3, keys2, keys1, pidx3, pidx2, x7p, x6p);

    // 1: enc1 [N3,1]->[N3,16]  OS=1 NPN=2  (512 CTAs, 576B)
    conv_kernel<1, 16, 1, 2, true, false><<<512, 256, 576>>>(
        features, neighs3, nullptr, N3, 16, w_enc1, b_enc1, x8);
    // 2: pool 3->2
    pool_kernel<16><<<cdiv(N3 * 16, 256), 256>>>(x8, pidx3, N3, N2, x7p);
    // 3: enc2 [N2,16]->[N2,32]  OS=2  (512 CTAs, 18KB)
    conv_kernel<16, 32, 2, 1, true, false><<<N2 * 2 / 256, 256, 18432>>>(
        x7p, neighs2, nullptr, N2, 32, w_enc2, b_enc2, x7);
    // 4: pool 2->1
    pool_kernel<32><<<cdiv(N2 * 32, 256), 256>>>(x7, pidx2, N2, N1, x6p);
    // 5: enc3 [N1,32]->[N1,64]  OS=4  (256 CTAs, 72KB)
    conv_kernel<32, 64, 4, 1, true, false><<<N1 * 4 / 256, 256, 73728>>>(
        x6p, neighs1, nullptr, N1, 64, w_enc3, b_enc3, x6);
    // 6: dec1 (unpool 1->2 fused) [N2,9*64]->[N2,32]  OS=2  (512 CTAs, 72KB)
    conv_kernel<64, 32, 2, 1, true, true><<<N2 * 2 / 256, 256, 73728>>>(
        x6, neighs2, pidx2, N1, 32, w_dec1, b_dec1, x7dec);
    // 7: dec2 (unpool 2->3 fused) [N3,9*32]->[N3,16]  OS=2  (2048 CTAs, 18KB)
    conv_kernel<32, 16, 2, 1, true, true><<<N3 * 2 / 256, 256, 18432>>>(
        x7dec, neighs3, pidx3, N2, 16, w_dec2, b_dec2, x8dec);
    // 8: head [N3,16]->[N3,1]  OS=1 NPN=2, no relu  (512 CTAs, 576B)
    conv_kernel<16, 1, 1, 2, false, false><<<512, 256, 576>>>(
        x8dec, neighs3, nullptr, N3, 1, w_head, b_head, out);
}